// round 7
// baseline (speedup 1.0000x reference)
#include <cuda_runtime.h>
#include <cuda_pipeline.h>
#include <math.h>

#define Nn 16
#define Ss 4
#define Cc 128
#define Hh 36
#define Ww 36
#define Uu 8000
#define Rr 4
#define HW (Hh*Ww)
#define NKEY (37*37)   // 1369 bilinear cells
#define IPB 16         // items per main block (8000 % 16 == 0 -> no s-crossing)
#define SEG 6          // keys per thread in 256-thread scan

// Scratch (device globals — no runtime allocation)
__device__ float  g_coreT[(size_t)Nn*Ss*HW*Cc];   // [n][s][p][c], 42.5 MB
__device__ int    g_offsets[NKEY+1];
__device__ int    g_sortedU[Uu];
__device__ int    g_cellId[Uu];                   // cell key per sorted slot
__device__ float4 g_wts[Uu];                      // w00,w01,w10,w11 per sorted slot

// ---------------------------------------------------------------------------
// Fused prep: z < Nn*Ss -> transpose (128c x 32p tile), z == Nn*Ss -> binsort
// ---------------------------------------------------------------------------
__device__ __forceinline__ int cell_key_w(const float* pos, int u,
                                          float& wx, float& wy) {
    float x = ((pos[2*u]   + 1.0f) * (float)Ww - 1.0f) * 0.5f;
    float y = ((pos[2*u+1] + 1.0f) * (float)Hh - 1.0f) * 0.5f;
    float xf = floorf(x), yf = floorf(y);
    wx = x - xf; wy = y - yf;
    int kx = (int)xf; kx = max(-1, min(kx, Ww-1));
    int ky = (int)yf; ky = max(-1, min(ky, Hh-1));
    return (ky+1)*37 + (kx+1);
}

__global__ void __launch_bounds__(256)
prep_kernel(const float* __restrict__ core, const float* __restrict__ pos) {
    __shared__ float tile[128*32];       // transpose: word(c,p)=c*32+(p^(c&31))
    __shared__ int   hist[NKEY];         // binsort path
    __shared__ int   curs[NKEY];
    __shared__ int   wtot[8];

    int t = threadIdx.x;

    if (blockIdx.z == (unsigned)(Nn*Ss)) {
        // ---------------- binsort (single block) ----------------
        if (blockIdx.x != 0) return;

        for (int i = t; i < NKEY; i += 256) hist[i] = 0;
        __syncthreads();

        for (int u = t; u < Uu; u += 256) {
            float wx, wy;
            int key = cell_key_w(pos, u, wx, wy);
            atomicAdd(&hist[key], 1);
        }
        __syncthreads();

        int lane = t & 31, wid = t >> 5;
        int lv[SEG];
        int run = 0;
        #pragma unroll
        for (int k = 0; k < SEG; k++) {
            int i = t*SEG + k;
            run += (i < NKEY) ? hist[i] : 0;
            lv[k] = run;
        }
        int tot = run;
        int inc = tot;
        #pragma unroll
        for (int d = 1; d < 32; d <<= 1) {
            int y = __shfl_up_sync(0xffffffffu, inc, d);
            if (lane >= d) inc += y;
        }
        if (lane == 31) wtot[wid] = inc;
        __syncthreads();
        if (t == 0) {
            int s = 0;
            #pragma unroll
            for (int w = 0; w < 8; w++) { int v = wtot[w]; wtot[w] = s; s += v; }
        }
        __syncthreads();
        int exc = wtot[wid] + (inc - tot);
        #pragma unroll
        for (int k = 0; k < SEG; k++) {
            int i = t*SEG + k;
            if (i < NKEY) {
                int off = exc + lv[k] - hist[i];
                g_offsets[i] = off;
                curs[i] = off;
            }
        }
        if (t == 0) g_offsets[NKEY] = Uu;
        __syncthreads();

        for (int u = t; u < Uu; u += 256) {
            float wx, wy;
            int key = cell_key_w(pos, u, wx, wy);
            int p = atomicAdd(&curs[key], 1);
            g_sortedU[p] = u;
            g_cellId[p]  = key;
            g_wts[p] = make_float4((1.0f-wx)*(1.0f-wy), wx*(1.0f-wy),
                                   (1.0f-wx)*wy,        wx*wy);
        }
        return;
    }

    // ---------------- transpose: 128 channels x 32 px ----------------
    int ns = blockIdx.z;
    int p0 = blockIdx.x * 32;

    int cl = t >> 3, q = t & 7;          // cl: 0..31 channel-in-group, q: px quad
    int p  = p0 + q*4;
    if (p < HW) {
        #pragma unroll
        for (int g = 0; g < 4; g++) {
            int c = g*32 + cl;
            float4 v = *(const float4*)(core + ((size_t)(ns*Cc + c))*HW + p);
            tile[c*32 + ((q*4+0) ^ cl)] = v.x;
            tile[c*32 + ((q*4+1) ^ cl)] = v.y;
            tile[c*32 + ((q*4+2) ^ cl)] = v.z;
            tile[c*32 + ((q*4+3) ^ cl)] = v.w;
        }
    }
    __syncthreads();

    int pl = t >> 3, cq = t & 7;
    int pg = p0 + pl;
    if (pg < HW) {
        #pragma unroll
        for (int g = 0; g < 4; g++) {
            int cbase = g*32 + cq*4;
            float4 o;
            o.x = tile[(cbase+0)*32 + (pl ^ ((cbase+0) & 31))];
            o.y = tile[(cbase+1)*32 + (pl ^ ((cbase+1) & 31))];
            o.z = tile[(cbase+2)*32 + (pl ^ ((cbase+2) & 31))];
            o.w = tile[(cbase+3)*32 + (pl ^ ((cbase+3) & 31))];
            *(float4*)(g_coreT + ((size_t)ns*HW + pg)*Cc + cbase) = o;
        }
    }
}

// ---------------------------------------------------------------------------
// Main: one block per 16-item slice of the flat sorted item list.
// All per-item data prefetched in one cp.async batch; compute loop sync-free.
// Corners reloaded (block-uniform) only on cell-run change; coreT is L2-hot.
// ---------------------------------------------------------------------------
__global__ void __launch_bounds__(256, 4)
main_kernel(const float* __restrict__ feature,
            const float* __restrict__ bias,
            float* __restrict__ out)
{
    int b    = blockIdx.x;
    int i0   = b * IPB;          // global item id
    int s    = i0 / Uu;          // constant within block (8000 % IPB == 0)
    int idx0 = i0 - s * Uu;      // first sorted-u index

    __shared__ float4 smF[IPB*128];   // feature rows (32 KB)
    __shared__ float4 smW[IPB];       // bilinear weights
    __shared__ float4 smB[IPB];       // bias
    __shared__ int    smU[IPB];       // u indices
    __shared__ int    smC[IPB];       // cell ids

    int t = threadIdx.x;

    // one-shot prefetch of everything the compute loop needs
    #pragma unroll
    for (int e2 = 0; e2 < IPB*128; e2 += 256) {
        int e = e2 + t;
        int u = g_sortedU[idx0 + (e >> 7)];
        const float4* src = (const float4*)feature
                          + (((size_t)(s*Uu + u)) << 7) + (e & 127);
        __pipeline_memcpy_async(&smF[e], src, 16);
    }
    if (t < IPB) {
        int u = g_sortedU[idx0 + t];
        __pipeline_memcpy_async(&smW[t], &g_wts[idx0 + t], 16);
        __pipeline_memcpy_async(&smB[t], (const float4*)bias + (size_t)(s*Uu + u), 16);
        __pipeline_memcpy_async(&smU[t], &g_sortedU[idx0 + t], 4);
        __pipeline_memcpy_async(&smC[t], &g_cellId[idx0 + t], 4);
    }
    __pipeline_commit();
    __pipeline_wait_prior(0);
    __syncthreads();

    int n   = t >> 4;
    int sub = t & 15;
    const float* baseT = g_coreT + ((size_t)(n*Ss + s))*HW*Cc + sub*8;

    float4 cv[4][2];
    int cur_cell = -1;

    #pragma unroll
    for (int ul = 0; ul < IPB; ul++) {
        int cell = smC[ul];
        if (cell != cur_cell) {          // block-uniform branch
            cur_cell = cell;
            int cx = cell % 37 - 1;
            int cy = cell / 37 - 1;
            int x0 = max(cx, 0), x1 = min(cx+1, Ww-1);
            int y0 = max(cy, 0), y1 = min(cy+1, Hh-1);
            int pix[4] = { y0*Ww + x0, y0*Ww + x1, y1*Ww + x0, y1*Ww + x1 };
            #pragma unroll
            for (int j = 0; j < 4; j++) {
                const float4* pj = (const float4*)(baseT + (size_t)pix[j]*Cc);
                cv[j][0] = pj[0];
                cv[j][1] = pj[1];
            }
        }

        float4 w = smW[ul];
        const float4* fb = &smF[ul*128];

        float acc0 = 0.f, acc1 = 0.f, acc2 = 0.f, acc3 = 0.f;
        #pragma unroll
        for (int j = 0; j < 2; j++) {
            float4 sv;
            sv.x = w.x*cv[0][j].x + w.y*cv[1][j].x + w.z*cv[2][j].x + w.w*cv[3][j].x;
            sv.y = w.x*cv[0][j].y + w.y*cv[1][j].y + w.z*cv[2][j].y + w.w*cv[3][j].y;
            sv.z = w.x*cv[0][j].z + w.y*cv[1][j].z + w.z*cv[2][j].z + w.w*cv[3][j].z;
            sv.w = w.x*cv[0][j].w + w.y*cv[1][j].w + w.z*cv[2][j].w + w.w*cv[3][j].w;

            int fi = sub*2 + j;
            float4 f0 = fb[0*32 + fi];
            float4 f1 = fb[1*32 + fi];
            float4 f2 = fb[2*32 + fi];
            float4 f3 = fb[3*32 + fi];
            acc0 += f0.x*sv.x + f0.y*sv.y + f0.z*sv.z + f0.w*sv.w;
            acc1 += f1.x*sv.x + f1.y*sv.y + f1.z*sv.z + f1.w*sv.w;
            acc2 += f2.x*sv.x + f2.y*sv.y + f2.z*sv.z + f2.w*sv.w;
            acc3 += f3.x*sv.x + f3.y*sv.y + f3.z*sv.z + f3.w*sv.w;
        }

        // 5-shuffle reduce over 16 sub-lanes; lane sub<4 ends with r=sub.
        bool p1b = sub & 1;
        float k01 = p1b ? acc1 : acc0;
        float s01 = p1b ? acc0 : acc1;
        k01 += __shfl_xor_sync(0xffffffffu, s01, 1, 16);
        float k23 = p1b ? acc3 : acc2;
        float s23 = p1b ? acc2 : acc3;
        k23 += __shfl_xor_sync(0xffffffffu, s23, 1, 16);
        bool p2b = sub & 2;
        float vk = p2b ? k23 : k01;
        float vs = p2b ? k01 : k23;
        vk += __shfl_xor_sync(0xffffffffu, vs, 2, 16);
        vk += __shfl_xor_sync(0xffffffffu, vk, 4, 16);
        vk += __shfl_xor_sync(0xffffffffu, vk, 8, 16);

        if (sub < 4) {
            int u = smU[ul];
            float bb = ((const float*)&smB[ul])[sub];
            out[(((size_t)(n*Ss + s))*Uu + u)*Rr + sub] = vk + bb;
        }
    }
}

// ---------------------------------------------------------------------------
extern "C" void kernel_launch(void* const* d_in, const int* in_sizes, int n_in,
                              void* d_out, int out_size) {
    const float* core      = (const float*)d_in[0];
    const float* positions = (const float*)d_in[1];
    const float* feature   = (const float*)d_in[2];
    const float* bias      = (const float*)d_in[3];
    float* out = (float*)d_out;

    dim3 tg((HW + 31)/32, 1, Nn*Ss + 1);   // last z-slice: binsort block
    prep_kernel<<<tg, 256>>>(core, positions);

    main_kernel<<<(Ss*Uu)/IPB, 256>>>(feature, bias, out);
}

// round 9
// speedup vs baseline: 1.2482x; 1.2482x over previous
#include <cuda_runtime.h>
#include <cuda_pipeline.h>
#include <math.h>

#define Nn 16
#define Ss 4
#define Cc 128
#define Hh 36
#define Ww 36
#define Uu 8000
#define Rr 4
#define HW (Hh*Ww)
#define NKEY (37*37)   // 1369 bilinear cells
#define UT 4           // items per pipeline stage
#define SEG 6          // keys per thread in 256-thread scan

// Scratch (device globals — no runtime allocation)
__device__ float  g_coreT[(size_t)Nn*Ss*HW*Cc];   // [n][s][p][c], 42.5 MB
__device__ int    g_offsets[NKEY+1];
__device__ int    g_sortedU[Uu];
__device__ float4 g_wts[Uu];                      // w00,w01,w10,w11 per sorted slot

// ---------------------------------------------------------------------------
// Fused prep: z < Nn*Ss -> transpose (32x32 tile, proven 21.9us), z==Nn*Ss -> binsort
// ---------------------------------------------------------------------------
__device__ __forceinline__ int cell_key_w(const float* pos, int u,
                                          float& wx, float& wy) {
    float x = ((pos[2*u]   + 1.0f) * (float)Ww - 1.0f) * 0.5f;
    float y = ((pos[2*u+1] + 1.0f) * (float)Hh - 1.0f) * 0.5f;
    float xf = floorf(x), yf = floorf(y);
    wx = x - xf; wy = y - yf;
    int kx = (int)xf; kx = max(-1, min(kx, Ww-1));
    int ky = (int)yf; ky = max(-1, min(ky, Hh-1));
    return (ky+1)*37 + (kx+1);
}

__global__ void __launch_bounds__(256)
prep_kernel(const float* __restrict__ core, const float* __restrict__ pos) {
    __shared__ float tile[32*32];        // transpose path
    __shared__ int   hist[NKEY];         // binsort path
    __shared__ int   curs[NKEY];
    __shared__ int   wtot[8];

    int t = threadIdx.x;

    if (blockIdx.z == (unsigned)(Nn*Ss)) {
        // ---------------- binsort (single block) ----------------
        if (blockIdx.x != 0 || blockIdx.y != 0) return;

        for (int i = t; i < NKEY; i += 256) hist[i] = 0;
        __syncthreads();

        for (int u = t; u < Uu; u += 256) {
            float wx, wy;
            int key = cell_key_w(pos, u, wx, wy);
            atomicAdd(&hist[key], 1);
        }
        __syncthreads();

        int lane = t & 31, wid = t >> 5;
        int lv[SEG];
        int run = 0;
        #pragma unroll
        for (int k = 0; k < SEG; k++) {
            int i = t*SEG + k;
            run += (i < NKEY) ? hist[i] : 0;
            lv[k] = run;
        }
        int tot = run;
        int inc = tot;
        #pragma unroll
        for (int d = 1; d < 32; d <<= 1) {
            int y = __shfl_up_sync(0xffffffffu, inc, d);
            if (lane >= d) inc += y;
        }
        if (lane == 31) wtot[wid] = inc;
        __syncthreads();
        if (t == 0) {
            int s = 0;
            #pragma unroll
            for (int w = 0; w < 8; w++) { int v = wtot[w]; wtot[w] = s; s += v; }
        }
        __syncthreads();
        int exc = wtot[wid] + (inc - tot);
        #pragma unroll
        for (int k = 0; k < SEG; k++) {
            int i = t*SEG + k;
            if (i < NKEY) {
                int off = exc + lv[k] - hist[i];
                g_offsets[i] = off;
                curs[i] = off;
            }
        }
        if (t == 0) g_offsets[NKEY] = Uu;
        __syncthreads();

        for (int u = t; u < Uu; u += 256) {
            float wx, wy;
            int key = cell_key_w(pos, u, wx, wy);
            int p = atomicAdd(&curs[key], 1);
            g_sortedU[p] = u;
            g_wts[p] = make_float4((1.0f-wx)*(1.0f-wy), wx*(1.0f-wy),
                                   (1.0f-wx)*wy,        wx*wy);
        }
        return;
    }

    // ---------------- transpose tile (32c x 32p, XOR swizzle) ----------------
    int ns = blockIdx.z;
    int c0 = blockIdx.y * 32;
    int p0 = blockIdx.x * 32;

    int cl = t >> 3, q = t & 7;
    int p  = p0 + q*4;
    if (p < HW) {
        float4 v = *(const float4*)(core + ((size_t)(ns*Cc + c0 + cl))*HW + p);
        tile[cl*32 + ((q*4+0) ^ cl)] = v.x;
        tile[cl*32 + ((q*4+1) ^ cl)] = v.y;
        tile[cl*32 + ((q*4+2) ^ cl)] = v.z;
        tile[cl*32 + ((q*4+3) ^ cl)] = v.w;
    }
    __syncthreads();

    int pl = t >> 3, cq = t & 7;
    int pg = p0 + pl;
    if (pg < HW) {
        float4 o;
        o.x = tile[(cq*4+0)*32 + (pl ^ (cq*4+0))];
        o.y = tile[(cq*4+1)*32 + (pl ^ (cq*4+1))];
        o.z = tile[(cq*4+2)*32 + (pl ^ (cq*4+2))];
        o.w = tile[(cq*4+3)*32 + (pl ^ (cq*4+3))];
        *(float4*)(g_coreT + ((size_t)ns*HW + pg)*Cc + c0 + cq*4) = o;
    }
}

// ---------------------------------------------------------------------------
// Main: grid (cell, s, nh). Block = 8 warps; warp = one n (nh*8 + wid),
// lane = 4-channel chunk. Corners (16 regs) loaded once; feature/weights/bias
// double-buffered via cp.async; items computed in PAIRS for 2x ILP.
// ---------------------------------------------------------------------------
__global__ void __launch_bounds__(256, 4)
main_kernel(const float* __restrict__ feature,
            const float* __restrict__ bias,
            float* __restrict__ out)
{
    int cell  = blockIdx.x;
    int s     = blockIdx.y;
    int nh    = blockIdx.z;
    int start = g_offsets[cell];
    int end   = g_offsets[cell+1];
    int cnt   = end - start;
    if (cnt == 0) return;

    int cx = cell % 37 - 1;
    int cy = cell / 37 - 1;
    int x0 = max(cx, 0), x1 = min(cx+1, Ww-1);
    int y0 = max(cy, 0), y1 = min(cy+1, Hh-1);
    int pix0 = y0*Ww + x0;   // w00
    int pix1 = y0*Ww + x1;   // w01
    int pix2 = y1*Ww + x0;   // w10
    int pix3 = y1*Ww + x1;   // w11

    int t    = threadIdx.x;
    int wid  = t >> 5;
    int lane = t & 31;
    int n    = nh*8 + wid;

    __shared__ float4 smF[2][UT*128];   // feature tiles (2 x 8 KB)
    __shared__ float4 smW[2][UT];       // bilinear weights
    __shared__ float4 smB[2][UT];       // bias
    __shared__ int    smU[2][UT];       // u indices

    int nTiles = (cnt + UT - 1) / UT;

    auto issue = [&](int tk, int bufi) {
        int tbase = start + tk*UT;
        int tcnt  = min(UT, end - tbase);
        #pragma unroll
        for (int e2 = 0; e2 < UT*128; e2 += 256) {
            int e = e2 + t;
            if (e < tcnt*128) {
                int u = g_sortedU[tbase + (e >> 7)];
                const float4* src = (const float4*)feature
                                  + (((size_t)(s*Uu + u)) << 7) + (e & 127);
                __pipeline_memcpy_async(&smF[bufi][e], src, 16);
            }
        }
        if (t < tcnt) {
            int u = g_sortedU[tbase + t];
            __pipeline_memcpy_async(&smW[bufi][t], &g_wts[tbase + t], 16);
            __pipeline_memcpy_async(&smB[bufi][t],
                                    (const float4*)bias + (size_t)(s*Uu + u), 16);
            __pipeline_memcpy_async(&smU[bufi][t], &g_sortedU[tbase + t], 4);
        }
    };

    issue(0, 0);
    __pipeline_commit();

    // One-time corner load: 4 corners x 4 channels (chans lane*4..lane*4+3)
    const float* baseT = g_coreT + ((size_t)(n*Ss + s))*HW*Cc + lane*4;
    float4 cv0 = *(const float4*)(baseT + (size_t)pix0*Cc);
    float4 cv1 = *(const float4*)(baseT + (size_t)pix1*Cc);
    float4 cv2 = *(const float4*)(baseT + (size_t)pix2*Cc);
    float4 cv3 = *(const float4*)(baseT + (size_t)pix3*Cc);

    for (int tk = 0; tk < nTiles; tk++) {
        int cur = tk & 1;
        if (tk + 1 < nTiles) {
            issue(tk + 1, cur ^ 1);
            __pipeline_commit();
            __pipeline_wait_prior(1);
        } else {
            __pipeline_wait_prior(0);
        }
        __syncthreads();

        int tcnt = min(UT, cnt - tk*UT);

        #pragma unroll
        for (int up = 0; up < UT; up += 2) {
            if (up >= tcnt) break;
            int  ulA = up;
            bool hasB = (up + 1 < tcnt);
            int  ulB = hasB ? up + 1 : up;    // clamp: compute garbage-free, skip store

            // --- item A accumulate ---
            float4 wA = smW[cur][ulA];
            const float4* fbA = &smF[cur][ulA*128];
            float4 svA;
            svA.x = wA.x*cv0.x + wA.y*cv1.x + wA.z*cv2.x + wA.w*cv3.x;
            svA.y = wA.x*cv0.y + wA.y*cv1.y + wA.z*cv2.y + wA.w*cv3.y;
            svA.z = wA.x*cv0.z + wA.y*cv1.z + wA.z*cv2.z + wA.w*cv3.z;
            svA.w = wA.x*cv0.w + wA.y*cv1.w + wA.z*cv2.w + wA.w*cv3.w;

            // --- item B accumulate ---
            float4 wB = smW[cur][ulB];
            const float4* fbB = &smF[cur][ulB*128];
            float4 svB;
            svB.x = wB.x*cv0.x + wB.y*cv1.x + wB.z*cv2.x + wB.w*cv3.x;
            svB.y = wB.x*cv0.y + wB.y*cv1.y + wB.z*cv2.y + wB.w*cv3.y;
            svB.z = wB.x*cv0.z + wB.y*cv1.z + wB.z*cv2.z + wB.w*cv3.z;
            svB.w = wB.x*cv0.w + wB.y*cv1.w + wB.z*cv2.w + wB.w*cv3.w;

            float aA0, aA1, aA2, aA3, aB0, aB1, aB2, aB3;
            {
                float4 f;
                f = fbA[0*32 + lane];
                aA0 = f.x*svA.x + f.y*svA.y + f.z*svA.z + f.w*svA.w;
                f = fbB[0*32 + lane];
                aB0 = f.x*svB.x + f.y*svB.y + f.z*svB.z + f.w*svB.w;
                f = fbA[1*32 + lane];
                aA1 = f.x*svA.x + f.y*svA.y + f.z*svA.z + f.w*svA.w;
                f = fbB[1*32 + lane];
                aB1 = f.x*svB.x + f.y*svB.y + f.z*svB.z + f.w*svB.w;
                f = fbA[2*32 + lane];
                aA2 = f.x*svA.x + f.y*svA.y + f.z*svA.z + f.w*svA.w;
                f = fbB[2*32 + lane];
                aB2 = f.x*svB.x + f.y*svB.y + f.z*svB.z + f.w*svB.w;
                f = fbA[3*32 + lane];
                aA3 = f.x*svA.x + f.y*svA.y + f.z*svA.z + f.w*svA.w;
                f = fbB[3*32 + lane];
                aB3 = f.x*svB.x + f.y*svB.y + f.z*svB.z + f.w*svB.w;
            }

            // --- interleaved 6-SHFL reduces over 32 lanes; lane<4 -> r=lane ---
            bool b0 = lane & 1;
            float kA01 = b0 ? aA1 : aA0, sA01 = b0 ? aA0 : aA1;
            float kB01 = b0 ? aB1 : aB0, sB01 = b0 ? aB0 : aB1;
            kA01 += __shfl_xor_sync(0xffffffffu, sA01, 1);
            kB01 += __shfl_xor_sync(0xffffffffu, sB01, 1);
            float kA23 = b0 ? aA3 : aA2, sA23 = b0 ? aA2 : aA3;
            float kB23 = b0 ? aB3 : aB2, sB23 = b0 ? aB2 : aB3;
            kA23 += __shfl_xor_sync(0xffffffffu, sA23, 1);
            kB23 += __shfl_xor_sync(0xffffffffu, sB23, 1);
            bool b1 = lane & 2;
            float vA = b1 ? kA23 : kA01, vsA = b1 ? kA01 : kA23;
            float vB = b1 ? kB23 : kB01, vsB = b1 ? kB01 : kB23;
            vA += __shfl_xor_sync(0xffffffffu, vsA, 2);
            vB += __shfl_xor_sync(0xffffffffu, vsB, 2);
            vA += __shfl_xor_sync(0xffffffffu, vA, 4);
            vB += __shfl_xor_sync(0xffffffffu, vB, 4);
            vA += __shfl_xor_sync(0xffffffffu, vA, 8);
            vB += __shfl_xor_sync(0xffffffffu, vB, 8);
            vA += __shfl_xor_sync(0xffffffffu, vA, 16);
            vB += __shfl_xor_sync(0xffffffffu, vB, 16);

            if (lane < 4) {
                int uA = smU[cur][ulA];
                float bbA = ((const float*)&smB[cur][ulA])[lane];
                out[(((size_t)(n*Ss + s))*Uu + uA)*Rr + lane] = vA + bbA;
                if (hasB) {
                    int uB = smU[cur][ulB];
                    float bbB = ((const float*)&smB[cur][ulB])[lane];
                    out[(((size_t)(n*Ss + s))*Uu + uB)*Rr + lane] = vB + bbB;
                }
            }
        }
        __syncthreads();   // buffer reads done before refill
    }
}

// ---------------------------------------------------------------------------
extern "C" void kernel_launch(void* const* d_in, const int* in_sizes, int n_in,
                              void* d_out, int out_size) {
    const float* core      = (const float*)d_in[0];
    const float* positions = (const float*)d_in[1];
    const float* feature   = (const float*)d_in[2];
    const float* bias      = (const float*)d_in[3];
    float* out = (float*)d_out;

    dim3 tg((HW + 31)/32, Cc/32, Nn*Ss + 1);   // last z-slice: binsort block
    prep_kernel<<<tg, 256>>>(core, positions);

    main_kernel<<<dim3(NKEY, Ss, 2), 256>>>(feature, bias, out);
}

// round 10
// speedup vs baseline: 1.7350x; 1.3899x over previous
#include <cuda_runtime.h>
#include <cuda_pipeline.h>
#include <math.h>

#define Nn 16
#define Ss 4
#define Cc 128
#define Hh 36
#define Ww 36
#define Uu 8000
#define Rr 4
#define HW (Hh*Ww)
#define NKEY (37*37)   // 1369 bilinear cells
#define UT 4           // items per pipeline stage
#define SEG 6          // keys per thread in 256-thread scan

// Scratch (device globals — no runtime allocation)
__device__ float  g_coreT[(size_t)Nn*Ss*HW*Cc];   // [n][s][p][c], 42.5 MB
__device__ int    g_offsets[NKEY+1];
__device__ int    g_sortedU[Uu];
__device__ float4 g_wts[Uu];                      // w00,w01,w10,w11 per sorted slot

// ---------------------------------------------------------------------------
// Fused prep: z < Nn*Ss -> transpose (32x32 tile), z == Nn*Ss -> binsort
// ---------------------------------------------------------------------------
__device__ __forceinline__ int cell_key_w(const float* pos, int u,
                                          float& wx, float& wy) {
    float x = ((pos[2*u]   + 1.0f) * (float)Ww - 1.0f) * 0.5f;
    float y = ((pos[2*u+1] + 1.0f) * (float)Hh - 1.0f) * 0.5f;
    float xf = floorf(x), yf = floorf(y);
    wx = x - xf; wy = y - yf;
    int kx = (int)xf; kx = max(-1, min(kx, Ww-1));
    int ky = (int)yf; ky = max(-1, min(ky, Hh-1));
    return (ky+1)*37 + (kx+1);
}

__global__ void __launch_bounds__(256)
prep_kernel(const float* __restrict__ core, const float* __restrict__ pos) {
    __shared__ float tile[32*32];        // transpose path
    __shared__ int   hist[NKEY];         // binsort path
    __shared__ int   curs[NKEY];
    __shared__ int   wtot[8];

    int t = threadIdx.x;

    if (blockIdx.z == (unsigned)(Nn*Ss)) {
        // ---------------- binsort (single block) ----------------
        if (blockIdx.x != 0 || blockIdx.y != 0) return;

        for (int i = t; i < NKEY; i += 256) hist[i] = 0;
        __syncthreads();

        for (int u = t; u < Uu; u += 256) {
            float wx, wy;
            int key = cell_key_w(pos, u, wx, wy);
            atomicAdd(&hist[key], 1);
        }
        __syncthreads();

        int lane = t & 31, wid = t >> 5;
        int lv[SEG];
        int run = 0;
        #pragma unroll
        for (int k = 0; k < SEG; k++) {
            int i = t*SEG + k;
            run += (i < NKEY) ? hist[i] : 0;
            lv[k] = run;
        }
        int tot = run;
        int inc = tot;
        #pragma unroll
        for (int d = 1; d < 32; d <<= 1) {
            int y = __shfl_up_sync(0xffffffffu, inc, d);
            if (lane >= d) inc += y;
        }
        if (lane == 31) wtot[wid] = inc;
        __syncthreads();
        if (t == 0) {
            int s = 0;
            #pragma unroll
            for (int w = 0; w < 8; w++) { int v = wtot[w]; wtot[w] = s; s += v; }
        }
        __syncthreads();
        int exc = wtot[wid] + (inc - tot);
        #pragma unroll
        for (int k = 0; k < SEG; k++) {
            int i = t*SEG + k;
            if (i < NKEY) {
                int off = exc + lv[k] - hist[i];
                g_offsets[i] = off;
                curs[i] = off;
            }
        }
        if (t == 0) g_offsets[NKEY] = Uu;
        __syncthreads();

        for (int u = t; u < Uu; u += 256) {
            float wx, wy;
            int key = cell_key_w(pos, u, wx, wy);
            int p = atomicAdd(&curs[key], 1);
            g_sortedU[p] = u;
            g_wts[p] = make_float4((1.0f-wx)*(1.0f-wy), wx*(1.0f-wy),
                                   (1.0f-wx)*wy,        wx*wy);
        }
        return;
    }

    // ---------------- transpose tile (32c x 32p, XOR swizzle) ----------------
    int ns = blockIdx.z;
    int c0 = blockIdx.y * 32;
    int p0 = blockIdx.x * 32;

    int cl = t >> 3, q = t & 7;
    int p  = p0 + q*4;
    if (p < HW) {
        float4 v = *(const float4*)(core + ((size_t)(ns*Cc + c0 + cl))*HW + p);
        tile[cl*32 + ((q*4+0) ^ cl)] = v.x;
        tile[cl*32 + ((q*4+1) ^ cl)] = v.y;
        tile[cl*32 + ((q*4+2) ^ cl)] = v.z;
        tile[cl*32 + ((q*4+3) ^ cl)] = v.w;
    }
    __syncthreads();

    int pl = t >> 3, cq = t & 7;
    int pg = p0 + pl;
    if (pg < HW) {
        float4 o;
        o.x = tile[(cq*4+0)*32 + (pl ^ (cq*4+0))];
        o.y = tile[(cq*4+1)*32 + (pl ^ (cq*4+1))];
        o.z = tile[(cq*4+2)*32 + (pl ^ (cq*4+2))];
        o.w = tile[(cq*4+3)*32 + (pl ^ (cq*4+3))];
        *(float4*)(g_coreT + ((size_t)ns*HW + pg)*Cc + c0 + cq*4) = o;
    }
}

// ---------------------------------------------------------------------------
// Main: grid (cell, s). Block = 8 warps; warp w serves n = {2w, 2w+1};
// lane = 4-channel chunk. Each feature float4 is loaded from smem ONCE and
// feeds two dot chains (one per n) -> feature LDS traffic halved.
// 9-SHFL staged reduce yields 8 results (2n x 4r) on lanes 0-7.
// ---------------------------------------------------------------------------
__global__ void __launch_bounds__(256, 4)
main_kernel(const float* __restrict__ feature,
            const float* __restrict__ bias,
            float* __restrict__ out)
{
    int cell  = blockIdx.x;
    int s     = blockIdx.y;
    int start = g_offsets[cell];
    int end   = g_offsets[cell+1];
    int cnt   = end - start;
    if (cnt == 0) return;

    int cx = cell % 37 - 1;
    int cy = cell / 37 - 1;
    int x0 = max(cx, 0), x1 = min(cx+1, Ww-1);
    int y0 = max(cy, 0), y1 = min(cy+1, Hh-1);
    int pix0 = y0*Ww + x0;   // w00
    int pix1 = y0*Ww + x1;   // w01
    int pix2 = y1*Ww + x0;   // w10
    int pix3 = y1*Ww + x1;   // w11

    int t    = threadIdx.x;
    int wid  = t >> 5;
    int lane = t & 31;

    __shared__ float4 smF[2][UT*128];   // feature tiles (2 x 8 KB)
    __shared__ float4 smW[2][UT];       // bilinear weights
    __shared__ float4 smB[2][UT];       // bias
    __shared__ int    smU[2][UT];       // u indices

    int nTiles = (cnt + UT - 1) / UT;

    auto issue = [&](int tk, int bufi) {
        int tbase = start + tk*UT;
        int tcnt  = min(UT, end - tbase);
        #pragma unroll
        for (int e2 = 0; e2 < UT*128; e2 += 256) {
            int e = e2 + t;
            if (e < tcnt*128) {
                int u = g_sortedU[tbase + (e >> 7)];
                const float4* src = (const float4*)feature
                                  + (((size_t)(s*Uu + u)) << 7) + (e & 127);
                __pipeline_memcpy_async(&smF[bufi][e], src, 16);
            }
        }
        if (t < tcnt) {
            int u = g_sortedU[tbase + t];
            __pipeline_memcpy_async(&smW[bufi][t], &g_wts[tbase + t], 16);
            __pipeline_memcpy_async(&smB[bufi][t],
                                    (const float4*)bias + (size_t)(s*Uu + u), 16);
            __pipeline_memcpy_async(&smU[bufi][t], &g_sortedU[tbase + t], 4);
        }
    };

    issue(0, 0);
    __pipeline_commit();

    // One-time corner load: 2 n's x 4 corners x 4 channels (chans lane*4..+3)
    float4 cv[2][4];
    #pragma unroll
    for (int nn = 0; nn < 2; nn++) {
        int n = wid*2 + nn;
        const float* baseT = g_coreT + ((size_t)(n*Ss + s))*HW*Cc + lane*4;
        cv[nn][0] = *(const float4*)(baseT + (size_t)pix0*Cc);
        cv[nn][1] = *(const float4*)(baseT + (size_t)pix1*Cc);
        cv[nn][2] = *(const float4*)(baseT + (size_t)pix2*Cc);
        cv[nn][3] = *(const float4*)(baseT + (size_t)pix3*Cc);
    }

    for (int tk = 0; tk < nTiles; tk++) {
        int cur = tk & 1;
        if (tk + 1 < nTiles) {
            issue(tk + 1, cur ^ 1);
            __pipeline_commit();
            __pipeline_wait_prior(1);
        } else {
            __pipeline_wait_prior(0);
        }
        __syncthreads();

        int tcnt = min(UT, cnt - tk*UT);

        #pragma unroll
        for (int ul = 0; ul < UT; ul++) {
            if (ul >= tcnt) break;

            float4 w = smW[cur][ul];
            const float4* fb = &smF[cur][ul*128];

            // per-n bilinear-combined corner vectors (4 channels each)
            float4 sv0, sv1;
            sv0.x = w.x*cv[0][0].x + w.y*cv[0][1].x + w.z*cv[0][2].x + w.w*cv[0][3].x;
            sv0.y = w.x*cv[0][0].y + w.y*cv[0][1].y + w.z*cv[0][2].y + w.w*cv[0][3].y;
            sv0.z = w.x*cv[0][0].z + w.y*cv[0][1].z + w.z*cv[0][2].z + w.w*cv[0][3].z;
            sv0.w = w.x*cv[0][0].w + w.y*cv[0][1].w + w.z*cv[0][2].w + w.w*cv[0][3].w;
            sv1.x = w.x*cv[1][0].x + w.y*cv[1][1].x + w.z*cv[1][2].x + w.w*cv[1][3].x;
            sv1.y = w.x*cv[1][0].y + w.y*cv[1][1].y + w.z*cv[1][2].y + w.w*cv[1][3].y;
            sv1.z = w.x*cv[1][0].z + w.y*cv[1][1].z + w.z*cv[1][2].z + w.w*cv[1][3].z;
            sv1.w = w.x*cv[1][0].w + w.y*cv[1][1].w + w.z*cv[1][2].w + w.w*cv[1][3].w;

            // one feature load feeds both n's
            float a00, a01, a02, a03, a10, a11, a12, a13;
            {
                float4 f;
                f = fb[0*32 + lane];
                a00 = f.x*sv0.x + f.y*sv0.y + f.z*sv0.z + f.w*sv0.w;
                a10 = f.x*sv1.x + f.y*sv1.y + f.z*sv1.z + f.w*sv1.w;
                f = fb[1*32 + lane];
                a01 = f.x*sv0.x + f.y*sv0.y + f.z*sv0.z + f.w*sv0.w;
                a11 = f.x*sv1.x + f.y*sv1.y + f.z*sv1.z + f.w*sv1.w;
                f = fb[2*32 + lane];
                a02 = f.x*sv0.x + f.y*sv0.y + f.z*sv0.z + f.w*sv0.w;
                a12 = f.x*sv1.x + f.y*sv1.y + f.z*sv1.z + f.w*sv1.w;
                f = fb[3*32 + lane];
                a03 = f.x*sv0.x + f.y*sv0.y + f.z*sv0.z + f.w*sv0.w;
                a13 = f.x*sv1.x + f.y*sv1.y + f.z*sv1.z + f.w*sv1.w;
            }

            // staged 9-SHFL reduce: lane bits -> b0,b1 = r, b2 = n-parity
            bool b0 = lane & 1;
            float k0_01 = b0 ? a01 : a00, s0_01 = b0 ? a00 : a01;
            k0_01 += __shfl_xor_sync(0xffffffffu, s0_01, 1);
            float k0_23 = b0 ? a03 : a02, s0_23 = b0 ? a02 : a03;
            k0_23 += __shfl_xor_sync(0xffffffffu, s0_23, 1);
            float k1_01 = b0 ? a11 : a10, s1_01 = b0 ? a10 : a11;
            k1_01 += __shfl_xor_sync(0xffffffffu, s1_01, 1);
            float k1_23 = b0 ? a13 : a12, s1_23 = b0 ? a12 : a13;
            k1_23 += __shfl_xor_sync(0xffffffffu, s1_23, 1);

            bool b1 = lane & 2;
            float v0 = b1 ? k0_23 : k0_01, vs0 = b1 ? k0_01 : k0_23;
            v0 += __shfl_xor_sync(0xffffffffu, vs0, 2);
            float v1 = b1 ? k1_23 : k1_01, vs1 = b1 ? k1_01 : k1_23;
            v1 += __shfl_xor_sync(0xffffffffu, vs1, 2);

            bool b2 = lane & 4;
            float z = b2 ? v1 : v0, zs = b2 ? v0 : v1;
            z += __shfl_xor_sync(0xffffffffu, zs, 4);
            z += __shfl_xor_sync(0xffffffffu, z, 8);
            z += __shfl_xor_sync(0xffffffffu, z, 16);

            if (lane < 8) {
                int r  = lane & 3;
                int n  = wid*2 + ((lane >> 2) & 1);
                int u  = smU[cur][ul];
                float bb = ((const float*)&smB[cur][ul])[r];
                out[(((size_t)(n*Ss + s))*Uu + u)*Rr + r] = z + bb;
            }
        }
        __syncthreads();   // buffer reads done before refill
    }
}

// ---------------------------------------------------------------------------
extern "C" void kernel_launch(void* const* d_in, const int* in_sizes, int n_in,
                              void* d_out, int out_size) {
    const float* core      = (const float*)d_in[0];
    const float* positions = (const float*)d_in[1];
    const float* feature   = (const float*)d_in[2];
    const float* bias      = (const float*)d_in[3];
    float* out = (float*)d_out;

    dim3 tg((HW + 31)/32, Cc/32, Nn*Ss + 1);   // last z-slice: binsort block
    prep_kernel<<<tg, 256>>>(core, positions);

    main_kernel<<<dim3(NKEY, Ss), 256>>>(feature, bias, out);
}

// round 11
// speedup vs baseline: 1.7686x; 1.0194x over previous
#include <cuda_runtime.h>
#include <cuda_pipeline.h>
#include <math.h>

#define Nn 16
#define Ss 4
#define Cc 128
#define Hh 36
#define Ww 36
#define Uu 8000
#define Rr 4
#define HW (Hh*Ww)
#define NKEY (37*37)   // 1369 bilinear cells
#define UT 4           // items per pipeline stage
#define SEG 6          // keys per thread in 256-thread scan

typedef unsigned long long u64t;

// ---- Blackwell packed-fp32 helpers (FFMA2 via PTX f32x2) -------------------
__device__ __forceinline__ u64t pack2(float lo, float hi) {
    u64t r;
    asm("mov.b64 %0, {%1, %2};" : "=l"(r) : "f"(lo), "f"(hi));
    return r;
}
__device__ __forceinline__ u64t fma2(u64t a, u64t b, u64t c) {
    u64t d;
    asm("fma.rn.f32x2 %0, %1, %2, %3;" : "=l"(d) : "l"(a), "l"(b), "l"(c));
    return d;
}
__device__ __forceinline__ u64t mul2(u64t a, u64t b) {
    u64t d;
    asm("mul.rn.f32x2 %0, %1, %2;" : "=l"(d) : "l"(a), "l"(b));
    return d;
}
__device__ __forceinline__ float hadd2(u64t a) {
    float lo, hi;
    asm("mov.b64 {%0, %1}, %2;" : "=f"(lo), "=f"(hi) : "l"(a));
    return lo + hi;
}

// Scratch (device globals — no runtime allocation)
__device__ float  g_coreT[(size_t)Nn*Ss*HW*Cc];   // [n][s][p][c], 42.5 MB
__device__ int    g_offsets[NKEY+1];
__device__ int    g_sortedU[Uu];
__device__ float4 g_wts[Uu];                      // w00,w01,w10,w11 per sorted slot

// ---------------------------------------------------------------------------
// Fused prep: z < Nn*Ss -> transpose (2 c-groups per block, MLP=2),
//             z == Nn*Ss -> binsort (block 0,0 only)
// ---------------------------------------------------------------------------
__device__ __forceinline__ int cell_key_w(const float* pos, int u,
                                          float& wx, float& wy) {
    float x = ((pos[2*u]   + 1.0f) * (float)Ww - 1.0f) * 0.5f;
    float y = ((pos[2*u+1] + 1.0f) * (float)Hh - 1.0f) * 0.5f;
    float xf = floorf(x), yf = floorf(y);
    wx = x - xf; wy = y - yf;
    int kx = (int)xf; kx = max(-1, min(kx, Ww-1));
    int ky = (int)yf; ky = max(-1, min(ky, Hh-1));
    return (ky+1)*37 + (kx+1);
}

__global__ void __launch_bounds__(256)
prep_kernel(const float* __restrict__ core, const float* __restrict__ pos) {
    __shared__ float tile[2][32*32];     // transpose path (two c-groups)
    __shared__ int   hist[NKEY];         // binsort path
    __shared__ int   curs[NKEY];
    __shared__ int   wtot[8];

    int t = threadIdx.x;

    if (blockIdx.z == (unsigned)(Nn*Ss)) {
        // ---------------- binsort (single block) ----------------
        if (blockIdx.x != 0 || blockIdx.y != 0) return;

        for (int i = t; i < NKEY; i += 256) hist[i] = 0;
        __syncthreads();

        for (int u = t; u < Uu; u += 256) {
            float wx, wy;
            int key = cell_key_w(pos, u, wx, wy);
            atomicAdd(&hist[key], 1);
        }
        __syncthreads();

        int lane = t & 31, wid = t >> 5;
        int lv[SEG];
        int run = 0;
        #pragma unroll
        for (int k = 0; k < SEG; k++) {
            int i = t*SEG + k;
            run += (i < NKEY) ? hist[i] : 0;
            lv[k] = run;
        }
        int tot = run;
        int inc = tot;
        #pragma unroll
        for (int d = 1; d < 32; d <<= 1) {
            int y = __shfl_up_sync(0xffffffffu, inc, d);
            if (lane >= d) inc += y;
        }
        if (lane == 31) wtot[wid] = inc;
        __syncthreads();
        if (t == 0) {
            int s = 0;
            #pragma unroll
            for (int w = 0; w < 8; w++) { int v = wtot[w]; wtot[w] = s; s += v; }
        }
        __syncthreads();
        int exc = wtot[wid] + (inc - tot);
        #pragma unroll
        for (int k = 0; k < SEG; k++) {
            int i = t*SEG + k;
            if (i < NKEY) {
                int off = exc + lv[k] - hist[i];
                g_offsets[i] = off;
                curs[i] = off;
            }
        }
        if (t == 0) g_offsets[NKEY] = Uu;
        __syncthreads();

        for (int u = t; u < Uu; u += 256) {
            float wx, wy;
            int key = cell_key_w(pos, u, wx, wy);
            int p = atomicAdd(&curs[key], 1);
            g_sortedU[p] = u;
            g_wts[p] = make_float4((1.0f-wx)*(1.0f-wy), wx*(1.0f-wy),
                                   (1.0f-wx)*wy,        wx*wy);
        }
        return;
    }

    // ---------------- transpose: 2 c-groups x 32 px, XOR swizzle ----------------
    int ns = blockIdx.z;
    int p0 = blockIdx.x * 32;

    int cl = t >> 3, q = t & 7;
    int p  = p0 + q*4;
    if (p < HW) {
        #pragma unroll
        for (int g = 0; g < 2; g++) {
            int c = blockIdx.y*64 + g*32 + cl;
            float4 v = *(const float4*)(core + ((size_t)(ns*Cc + c))*HW + p);
            tile[g][cl*32 + ((q*4+0) ^ cl)] = v.x;
            tile[g][cl*32 + ((q*4+1) ^ cl)] = v.y;
            tile[g][cl*32 + ((q*4+2) ^ cl)] = v.z;
            tile[g][cl*32 + ((q*4+3) ^ cl)] = v.w;
        }
    }
    __syncthreads();

    int pl = t >> 3, cq = t & 7;
    int pg = p0 + pl;
    if (pg < HW) {
        #pragma unroll
        for (int g = 0; g < 2; g++) {
            float4 o;
            o.x = tile[g][(cq*4+0)*32 + (pl ^ (cq*4+0))];
            o.y = tile[g][(cq*4+1)*32 + (pl ^ (cq*4+1))];
            o.z = tile[g][(cq*4+2)*32 + (pl ^ (cq*4+2))];
            o.w = tile[g][(cq*4+3)*32 + (pl ^ (cq*4+3))];
            *(float4*)(g_coreT + ((size_t)ns*HW + pg)*Cc
                       + blockIdx.y*64 + g*32 + cq*4) = o;
        }
    }
}

// ---------------------------------------------------------------------------
// Main: grid (cell, s). Block = 8 warps; warp w serves n = {2w, 2w+1};
// lane = 4-channel chunk. f32x2 packed FFMA for bilinear + dot; one feature
// LDS.128 feeds both n's. 9-SHFL staged reduce -> 8 results on lanes 0-7.
// ---------------------------------------------------------------------------
__global__ void __launch_bounds__(256, 4)
main_kernel(const float* __restrict__ feature,
            const float* __restrict__ bias,
            float* __restrict__ out)
{
    int cell  = blockIdx.x;
    int s     = blockIdx.y;
    int start = g_offsets[cell];
    int end   = g_offsets[cell+1];
    int cnt   = end - start;
    if (cnt == 0) return;

    int cx = cell % 37 - 1;
    int cy = cell / 37 - 1;
    int x0 = max(cx, 0), x1 = min(cx+1, Ww-1);
    int y0 = max(cy, 0), y1 = min(cy+1, Hh-1);
    int pixs[4] = { y0*Ww + x0, y0*Ww + x1, y1*Ww + x0, y1*Ww + x1 };

    int t    = threadIdx.x;
    int wid  = t >> 5;
    int lane = t & 31;

    __shared__ float4 smF[2][UT*128];   // feature tiles (2 x 8 KB)
    __shared__ float4 smW[2][UT];       // bilinear weights
    __shared__ float4 smB[2][UT];       // bias
    __shared__ int    smU[2][UT];       // u indices

    int nTiles = (cnt + UT - 1) / UT;

    auto issue = [&](int tk, int bufi) {
        int tbase = start + tk*UT;
        int tcnt  = min(UT, end - tbase);
        #pragma unroll
        for (int e2 = 0; e2 < UT*128; e2 += 256) {
            int e = e2 + t;
            if (e < tcnt*128) {
                int u = g_sortedU[tbase + (e >> 7)];
                const float4* src = (const float4*)feature
                                  + (((size_t)(s*Uu + u)) << 7) + (e & 127);
                __pipeline_memcpy_async(&smF[bufi][e], src, 16);
            }
        }
        if (t < tcnt) {
            int u = g_sortedU[tbase + t];
            __pipeline_memcpy_async(&smW[bufi][t], &g_wts[tbase + t], 16);
            __pipeline_memcpy_async(&smB[bufi][t],
                                    (const float4*)bias + (size_t)(s*Uu + u), 16);
            __pipeline_memcpy_async(&smU[bufi][t], &g_sortedU[tbase + t], 4);
        }
    };

    issue(0, 0);
    __pipeline_commit();

    // One-time corner load as packed f32 pairs: 2n x 4 corners x 2 pairs
    u64t cvp[2][4][2];
    #pragma unroll
    for (int nn = 0; nn < 2; nn++) {
        int n = wid*2 + nn;
        const float* baseT = g_coreT + ((size_t)(n*Ss + s))*HW*Cc + lane*4;
        #pragma unroll
        for (int k = 0; k < 4; k++) {
            ulonglong2 v = *(const ulonglong2*)(baseT + (size_t)pixs[k]*Cc);
            cvp[nn][k][0] = v.x;
            cvp[nn][k][1] = v.y;
        }
    }

    for (int tk = 0; tk < nTiles; tk++) {
        int cur = tk & 1;
        if (tk + 1 < nTiles) {
            issue(tk + 1, cur ^ 1);
            __pipeline_commit();
            __pipeline_wait_prior(1);
        } else {
            __pipeline_wait_prior(0);
        }
        __syncthreads();

        int tcnt = min(UT, cnt - tk*UT);

        #pragma unroll
        for (int ul = 0; ul < UT; ul++) {
            if (ul >= tcnt) break;

            float4 w = smW[cur][ul];
            u64t wp0 = pack2(w.x, w.x);
            u64t wp1 = pack2(w.y, w.y);
            u64t wp2 = pack2(w.z, w.z);
            u64t wp3 = pack2(w.w, w.w);

            // bilinear-combined corner pairs per n (16 FFMA2-class ops)
            u64t sv[2][2];
            #pragma unroll
            for (int nn = 0; nn < 2; nn++) {
                #pragma unroll
                for (int pr = 0; pr < 2; pr++) {
                    sv[nn][pr] = fma2(wp0, cvp[nn][0][pr],
                                 fma2(wp1, cvp[nn][1][pr],
                                 fma2(wp2, cvp[nn][2][pr],
                                 mul2(wp3, cvp[nn][3][pr]))));
                }
            }

            // dots: one LDS.128 per r feeds both n's (16 FFMA2 + 8 hadd)
            const ulonglong2* fbu = (const ulonglong2*)&smF[cur][ul*128];
            float a00, a01, a02, a03, a10, a11, a12, a13;
            {
                ulonglong2 f;
                f = fbu[0*32 + lane];
                a00 = hadd2(fma2(f.x, sv[0][0], mul2(f.y, sv[0][1])));
                a10 = hadd2(fma2(f.x, sv[1][0], mul2(f.y, sv[1][1])));
                f = fbu[1*32 + lane];
                a01 = hadd2(fma2(f.x, sv[0][0], mul2(f.y, sv[0][1])));
                a11 = hadd2(fma2(f.x, sv[1][0], mul2(f.y, sv[1][1])));
                f = fbu[2*32 + lane];
                a02 = hadd2(fma2(f.x, sv[0][0], mul2(f.y, sv[0][1])));
                a12 = hadd2(fma2(f.x, sv[1][0], mul2(f.y, sv[1][1])));
                f = fbu[3*32 + lane];
                a03 = hadd2(fma2(f.x, sv[0][0], mul2(f.y, sv[0][1])));
                a13 = hadd2(fma2(f.x, sv[1][0], mul2(f.y, sv[1][1])));
            }

            // staged 9-SHFL reduce: lane bits -> b0,b1 = r, b2 = n-parity
            bool b0 = lane & 1;
            float k0_01 = b0 ? a01 : a00, s0_01 = b0 ? a00 : a01;
            k0_01 += __shfl_xor_sync(0xffffffffu, s0_01, 1);
            float k0_23 = b0 ? a03 : a02, s0_23 = b0 ? a02 : a03;
            k0_23 += __shfl_xor_sync(0xffffffffu, s0_23, 1);
            float k1_01 = b0 ? a11 : a10, s1_01 = b0 ? a10 : a11;
            k1_01 += __shfl_xor_sync(0xffffffffu, s1_01, 1);
            float k1_23 = b0 ? a13 : a12, s1_23 = b0 ? a12 : a13;
            k1_23 += __shfl_xor_sync(0xffffffffu, s1_23, 1);

            bool b1 = lane & 2;
            float v0 = b1 ? k0_23 : k0_01, vs0 = b1 ? k0_01 : k0_23;
            v0 += __shfl_xor_sync(0xffffffffu, vs0, 2);
            float v1 = b1 ? k1_23 : k1_01, vs1 = b1 ? k1_01 : k1_23;
            v1 += __shfl_xor_sync(0xffffffffu, vs1, 2);

            bool b2 = lane & 4;
            float z = b2 ? v1 : v0, zs = b2 ? v0 : v1;
            z += __shfl_xor_sync(0xffffffffu, zs, 4);
            z += __shfl_xor_sync(0xffffffffu, z, 8);
            z += __shfl_xor_sync(0xffffffffu, z, 16);

            if (lane < 8) {
                int r  = lane & 3;
                int n  = wid*2 + ((lane >> 2) & 1);
                int u  = smU[cur][ul];
                float bb = ((const float*)&smB[cur][ul])[r];
                out[(((size_t)(n*Ss + s))*Uu + u)*Rr + r] = z + bb;
            }
        }
        __syncthreads();   // buffer reads done before refill
    }
}

// ---------------------------------------------------------------------------
extern "C" void kernel_launch(void* const* d_in, const int* in_sizes, int n_in,
                              void* d_out, int out_size) {
    const float* core      = (const float*)d_in[0];
    const float* positions = (const float*)d_in[1];
    const float* feature   = (const float*)d_in[2];
    const float* bias      = (const float*)d_in[3];
    float* out = (float*)d_out;

    dim3 tg((HW + 31)/32, Cc/64, Nn*Ss + 1);   // last z-slice: binsort block
    prep_kernel<<<tg, 256>>>(core, positions);

    main_kernel<<<dim3(NKEY, Ss), 256>>>(feature, bias, out);
}